// round 4
// baseline (speedup 1.0000x reference)
#include <cuda_runtime.h>

// Problem constants
#define BB    64    // batch
#define WDIM  128   // node feature dim (K of projection)
#define FDIM  64    // number of nodes
#define HH    4     // heads
#define DOUT  128   // out window per head
// per-(b,h) tile: FDIM x DOUT = 64*128 = 8192 floats

// Scratch (device globals; allocation-free)
__device__ float g_fs[BB * HH * FDIM * DOUT];   // [b][h][i][d]
__device__ float g_fd[BB * HH * FDIM * DOUT];   // [b][h][j][d]
__device__ float g_oh[BB * HH * FDIM * DOUT];   // [b][h][j][d] per-head outputs

// ---------------------------------------------------------------------------
// Kernel 1: projections.  fs[b,i,h,d] = sum_w x[b,w,i] * W_src[h*128+d, w] + b_src
// grid (64, 8): blockIdx.y = ctile; ctile 0..3 -> fs head=ctile, 4..7 -> fd head=ctile-4
// block computes [64 rows (i)] x [128 cols (d)] with K=128.
// smem: As[128k][64r] (32KB) + Bs[128k][128c] (64KB) = 96KB dynamic.
// ---------------------------------------------------------------------------
__global__ __launch_bounds__(256, 2)
void proj_kernel(const float* __restrict__ x,
                 const float* __restrict__ Wsrc, const float* __restrict__ bsrc,
                 const float* __restrict__ Wdst, const float* __restrict__ bdst)
{
    extern __shared__ float sm[];
    float* As = sm;               // [k][r], stride 64
    float* Bs = sm + 128 * 64;    // [k][c], stride 128

    const int b  = blockIdx.x;
    const int ct = blockIdx.y;
    const int t  = threadIdx.x;

    const float* Wmat = (ct < 4) ? Wsrc : Wdst;
    const float* bias = (ct < 4) ? bsrc : bdst;
    const int c0 = (ct & 3) * 128;   // column offset inside the 512-wide matrix

    // Load A: x[b] is [128 w][64 f] contiguous -> As[w][f] directly (no transpose needed)
    {
        const float4* xb  = (const float4*)(x + (size_t)b * WDIM * FDIM);
        float4*       As4 = (float4*)As;
        #pragma unroll
        for (int idx = t; idx < 128 * 16; idx += 256) As4[idx] = xb[idx];
    }
    // Load B transposed: Bs[k][c] = Wmat[c0+c][k].
    // Lane-per-column scheme keeps STS conflict-free (lanes write consecutive c).
    for (int idx = t; idx < 128 * 32; idx += 256) {
        int c  = idx & 127;
        int kq = idx >> 7;   // 0..31
        float4 v = *(const float4*)(Wmat + (size_t)(c0 + c) * WDIM + kq * 4);
        Bs[(kq * 4 + 0) * 128 + c] = v.x;
        Bs[(kq * 4 + 1) * 128 + c] = v.y;
        Bs[(kq * 4 + 2) * 128 + c] = v.z;
        Bs[(kq * 4 + 3) * 128 + c] = v.w;
    }
    __syncthreads();

    const int tx = t & 15, ty = t >> 4;
    const int r0 = ty * 4;        // 4 rows per thread
    const int cc = tx * 8;        // 8 cols per thread

    float acc[4][8];
    #pragma unroll
    for (int r = 0; r < 4; r++)
        #pragma unroll
        for (int c = 0; c < 8; c++) acc[r][c] = 0.f;

    #pragma unroll 8
    for (int k = 0; k < 128; k++) {
        float4 a  = *(const float4*)&As[k * 64 + r0];
        float4 b0 = *(const float4*)&Bs[k * 128 + cc];
        float4 b1 = *(const float4*)&Bs[k * 128 + cc + 4];
        float av[4] = {a.x, a.y, a.z, a.w};
        float bv[8] = {b0.x, b0.y, b0.z, b0.w, b1.x, b1.y, b1.z, b1.w};
        #pragma unroll
        for (int r = 0; r < 4; r++)
            #pragma unroll
            for (int c = 0; c < 8; c++)
                acc[r][c] = fmaf(av[r], bv[c], acc[r][c]);
    }

    // Epilogue: add bias, store into g_fs/g_fd at [b][h][i][d]
    float* outbase = ((ct < 4) ? g_fs : g_fd)
                   + (size_t)b * HH * FDIM * DOUT + (size_t)(ct & 3) * FDIM * DOUT;
    float bv0[8];
    #pragma unroll
    for (int c = 0; c < 8; c++) bv0[c] = bias[c0 + cc + c];

    #pragma unroll
    for (int r = 0; r < 4; r++) {
        float4 o0 = make_float4(acc[r][0] + bv0[0], acc[r][1] + bv0[1],
                                acc[r][2] + bv0[2], acc[r][3] + bv0[3]);
        float4 o1 = make_float4(acc[r][4] + bv0[4], acc[r][5] + bv0[5],
                                acc[r][6] + bv0[6], acc[r][7] + bv0[7]);
        float* row = outbase + (size_t)(r0 + r) * DOUT + cc;
        *(float4*)(row)     = o0;
        *(float4*)(row + 4) = o1;
    }
}

// ---------------------------------------------------------------------------
// Kernel 2: fused scores + softmax + aggregation, one CTA per (b,h).
// score[i,j] = As[i] + Ad[j] - 0.8 * sum_d attn[d] * min(fs[i,d] + fd[j,d], 0)
//   (exact rewrite of sum_d attn[d]*leakyrelu(fs+fd, 0.2))
// softmax over i per j; oh[j,d] = sum_i p[i,j] * fs[i,d]
// smem: fsT/fdT stored [d][i] with stride 65 -> conflict-free in both phases.
// ---------------------------------------------------------------------------
__global__ __launch_bounds__(256, 2)
void attn_kernel(const float* __restrict__ attn)
{
    extern __shared__ float sm[];
    float* fsT   = sm;                 // [128 d][65] (i in 0..63)
    float* fdT   = fsT + 128 * 65;     // [128 d][65]
    float* attn3 = fdT + 128 * 65;     // 128  (-0.8 * attn[h])
    float* attnv = attn3 + 128;        // 128
    float* As_s  = attnv + 128;        // 64
    float* Ad_s  = As_s + 64;          // 64
    float* prob  = Ad_s + 64;          // [8 warps][8 j][64 i]

    const int bh   = blockIdx.x;       // b*4 + h
    const int h    = bh & 3;
    const int t    = threadIdx.x;
    const int lane = t & 31;
    const int w    = t >> 5;

    const float* fs = g_fs + (size_t)bh * FDIM * DOUT;
    const float* fd = g_fd + (size_t)bh * FDIM * DOUT;

    // Stage fs/fd transposed into smem (coalesced loads, conflict-free STS)
    for (int idx = t; idx < FDIM * DOUT; idx += 256) {
        int i = idx >> 7, d = idx & 127;
        fsT[d * 65 + i] = fs[idx];
        fdT[d * 65 + i] = fd[idx];
    }
    if (t < 128) {
        float a = attn[h * 128 + t];
        attnv[t] = a;
        attn3[t] = -0.8f * a;
    }
    __syncthreads();

    // As[i] = sum_d attn[d]*fs[i,d];  Ad[j] likewise with fd
    if (t < 64) {
        float s = 0.f;
        #pragma unroll 4
        for (int d = 0; d < 128; d++) s = fmaf(attnv[d], fsT[d * 65 + t], s);
        As_s[t] = s;
    } else if (t < 128) {
        int j = t - 64;
        float s = 0.f;
        #pragma unroll 4
        for (int d = 0; d < 128; d++) s = fmaf(attnv[d], fdT[d * 65 + j], s);
        Ad_s[j] = s;
    }
    __syncthreads();

    // ---- Score phase: warp w owns j = w*8 .. w*8+7; lane owns i = lane, lane+32
    const int jb = w * 8;
    float acc[8][2];
    #pragma unroll
    for (int jj = 0; jj < 8; jj++) acc[jj][0] = acc[jj][1] = 0.f;

    #pragma unroll 2
    for (int d = 0; d < 128; d++) {
        const float a3 = attn3[d];
        const float f0 = fsT[d * 65 + lane];
        const float f1 = fsT[d * 65 + 32 + lane];
        #pragma unroll
        for (int jj = 0; jj < 8; jj++) {
            float fdv = fdT[d * 65 + jb + jj];
            float s0 = f0 + fdv;
            float s1 = f1 + fdv;
            acc[jj][0] = fmaf(a3, fminf(s0, 0.f), acc[jj][0]);
            acc[jj][1] = fmaf(a3, fminf(s1, 0.f), acc[jj][1]);
        }
    }

    // ---- Softmax over i (64 sources) per j
    const float As0 = As_s[lane], As1 = As_s[lane + 32];
    #pragma unroll
    for (int jj = 0; jj < 8; jj++) {
        float Adv = Ad_s[jb + jj];
        float s0 = acc[jj][0] + As0 + Adv;
        float s1 = acc[jj][1] + As1 + Adv;
        float m = fmaxf(s0, s1);
        #pragma unroll
        for (int o = 16; o; o >>= 1) m = fmaxf(m, __shfl_xor_sync(0xffffffffu, m, o));
        float e0 = __expf(s0 - m);
        float e1 = __expf(s1 - m);
        float ssum = e0 + e1;
        #pragma unroll
        for (int o = 16; o; o >>= 1) ssum += __shfl_xor_sync(0xffffffffu, ssum, o);
        float inv = __frcp_rn(ssum);
        prob[(w * 8 + jj) * 64 + lane]      = e0 * inv;
        prob[(w * 8 + jj) * 64 + lane + 32] = e1 * inv;
    }
    __syncwarp();

    // ---- Aggregation: lane owns d = lane + 32*dd (dd=0..3), 8 j's register-blocked
    float o[8][4];
    #pragma unroll
    for (int jj = 0; jj < 8; jj++)
        #pragma unroll
        for (int dd = 0; dd < 4; dd++) o[jj][dd] = 0.f;

    #pragma unroll 2
    for (int i = 0; i < 64; i++) {
        float f[4];
        #pragma unroll
        for (int dd = 0; dd < 4; dd++) f[dd] = fsT[(lane + 32 * dd) * 65 + i];
        #pragma unroll
        for (int jj = 0; jj < 8; jj++) {
            float p = prob[(w * 8 + jj) * 64 + i];
            #pragma unroll
            for (int dd = 0; dd < 4; dd++) o[jj][dd] = fmaf(p, f[dd], o[jj][dd]);
        }
    }

    float* oh = g_oh + (size_t)bh * FDIM * DOUT;
    #pragma unroll
    for (int jj = 0; jj < 8; jj++)
        #pragma unroll
        for (int dd = 0; dd < 4; dd++)
            oh[(jb + jj) * DOUT + lane + 32 * dd] = o[jj][dd];
}

// ---------------------------------------------------------------------------
// Kernel 3: mean over heads + transpose.  out[b, d, j] = 0.25 * sum_h oh[b,h,j,d]
// ---------------------------------------------------------------------------
__global__ __launch_bounds__(256)
void reduce_kernel(float* __restrict__ out)
{
    __shared__ float s[64 * 129];
    const int b = blockIdx.x;
    const int t = threadIdx.x;
    const float* oh = g_oh + (size_t)b * HH * FDIM * DOUT;

    for (int idx = t; idx < FDIM * DOUT; idx += 256) {
        int j = idx >> 7, d = idx & 127;
        float v = oh[idx] + oh[idx + 8192] + oh[idx + 16384] + oh[idx + 24576];
        s[j * 129 + d] = 0.25f * v;
    }
    __syncthreads();

    float* ob = out + (size_t)b * DOUT * FDIM;
    for (int idx = t; idx < DOUT * FDIM; idx += 256) {
        int j = idx & 63, d = idx >> 6;
        ob[idx] = s[j * 129 + d];
    }
}

// ---------------------------------------------------------------------------
extern "C" void kernel_launch(void* const* d_in, const int* in_sizes, int n_in,
                              void* d_out, int out_size)
{
    const float* x    = (const float*)d_in[0];
    const float* Wsrc = (const float*)d_in[1];
    const float* bsrc = (const float*)d_in[2];
    const float* Wdst = (const float*)d_in[3];
    const float* bdst = (const float*)d_in[4];
    const float* attn = (const float*)d_in[5];
    float* out = (float*)d_out;

    const int smem1 = (128 * 64 + 128 * 128) * 4;                        // 96 KB
    const int smem2 = (128 * 65 * 2 + 128 + 128 + 64 + 64 + 4096) * 4;   // 84480 B

    cudaFuncSetAttribute(proj_kernel, cudaFuncAttributeMaxDynamicSharedMemorySize, smem1);
    cudaFuncSetAttribute(attn_kernel, cudaFuncAttributeMaxDynamicSharedMemorySize, smem2);

    proj_kernel<<<dim3(BB, 8), 256, smem1>>>(x, Wsrc, bsrc, Wdst, bdst);
    attn_kernel<<<BB * HH, 256, smem2>>>(attn);
    reduce_kernel<<<BB, 256>>>(out);
}

// round 5
// speedup vs baseline: 1.2882x; 1.2882x over previous
#include <cuda_runtime.h>

typedef unsigned long long ull;

// Problem constants
#define BB    64    // batch
#define WDIM  128   // node feature dim (K of projection)
#define FDIM  64    // number of nodes
#define HH    4     // heads
#define DOUT  128   // out window per head

// Scratch (device globals; allocation-free)
__device__ float g_fs[BB * HH * FDIM * DOUT];   // [b][h][i][d]
__device__ float g_fd[BB * HH * FDIM * DOUT];   // [b][h][j][d]
__device__ float g_oh[BB * HH * FDIM * DOUT];   // [b][h][j][d] per-head outputs

// ---------------------------------------------------------------------------
// f32x2 packed-math helpers (Blackwell FFMA2 path — PTX only, ptxas never
// auto-fuses).  A ull holds {lo=f0, hi=f1} as a packed fp32 pair.
// ---------------------------------------------------------------------------
__device__ __forceinline__ ull fma2(ull a, ull b, ull c) {
    asm("fma.rn.f32x2 %0, %1, %2, %0;" : "+l"(c) : "l"(a), "l"(b));
    return c;
}
__device__ __forceinline__ ull add2(ull a, ull b) {
    ull d; asm("add.rn.f32x2 %0, %1, %2;" : "=l"(d) : "l"(a), "l"(b));
    return d;
}
__device__ __forceinline__ ull dup2(float x) {
    ull d; asm("mov.b64 %0, {%1, %1};" : "=l"(d) : "f"(x));
    return d;
}
__device__ __forceinline__ float2 u2f(ull v) {
    float2 f; asm("mov.b64 {%0, %1}, %2;" : "=f"(f.x), "=f"(f.y) : "l"(v));
    return f;
}
__device__ __forceinline__ ull abs2(ull v) {          // 2x LOP3 on alu pipe
    return v & 0x7fffffff7fffffffULL;
}

// ---------------------------------------------------------------------------
// Kernel 1: projections via FFMA2.
// grid (64, 8): ctile 0..3 -> fs head=ct, 4..7 -> fd head=ct-4.
// CTA tile: 64 rows (i) x 128 cols (d), K=128.  256 threads.
// Thread tile: 8 rows x 4 cols = 16 FFMA2 per k.
// Accumulators pack ROW PAIRS, so A float4 loads reinterpret directly as
// packed operands (no dup MOVs); only B needs 4 dup-packs per k.
// ---------------------------------------------------------------------------
__global__ __launch_bounds__(256, 2)
void proj_kernel(const float* __restrict__ x,
                 const float* __restrict__ Wsrc, const float* __restrict__ bsrc,
                 const float* __restrict__ Wdst, const float* __restrict__ bdst)
{
    extern __shared__ float sm[];
    float* As = sm;               // [k][r], stride 64  (32 KB)
    float* Bs = sm + 128 * 64;    // [k][c], stride 128 (64 KB)

    const int b  = blockIdx.x;
    const int ct = blockIdx.y;
    const int t  = threadIdx.x;

    const float* Wmat = (ct < 4) ? Wsrc : Wdst;
    const float* bias = (ct < 4) ? bsrc : bdst;
    const int c0 = (ct & 3) * 128;

    // Load A: x[b] is [128 w][64 f] contiguous -> As[w][f] directly
    {
        const float4* xb  = (const float4*)(x + (size_t)b * WDIM * FDIM);
        float4*       As4 = (float4*)As;
        #pragma unroll
        for (int idx = t; idx < 128 * 16; idx += 256) As4[idx] = xb[idx];
    }
    // Load B transposed: Bs[k][c] = Wmat[c0+c][k]
    for (int idx = t; idx < 128 * 32; idx += 256) {
        int c  = idx & 127;
        int kq = idx >> 7;
        float4 v = *(const float4*)(Wmat + (size_t)(c0 + c) * WDIM + kq * 4);
        Bs[(kq * 4 + 0) * 128 + c] = v.x;
        Bs[(kq * 4 + 1) * 128 + c] = v.y;
        Bs[(kq * 4 + 2) * 128 + c] = v.z;
        Bs[(kq * 4 + 3) * 128 + c] = v.w;
    }
    __syncthreads();

    const int cx = t & 31;        // 32 col-threads * 4 cols = 128 cols
    const int ry = t >> 5;        // 8 row-threads (= warp id) * 8 rows = 64 rows
    // lanes within a warp share ry -> A loads are warp-broadcast LDS.128
    // B loads: lanes at 16B stride -> conflict-free LDS.128

    ull acc2[4][4];               // [row-pair][col], lo = even row, hi = odd
    #pragma unroll
    for (int rp = 0; rp < 4; rp++)
        #pragma unroll
        for (int c = 0; c < 4; c++) acc2[rp][c] = 0ULL;

    #pragma unroll 4
    for (int k = 0; k < 128; k++) {
        float4 a0 = *(const float4*)&As[k * 64 + ry * 8];
        float4 a1 = *(const float4*)&As[k * 64 + ry * 8 + 4];
        float4 bq = *(const float4*)&Bs[k * 128 + cx * 4];
        const ull* av0 = (const ull*)&a0;   // row pairs (r0,r1),(r2,r3)
        const ull* av1 = (const ull*)&a1;   // row pairs (r4,r5),(r6,r7)
        ull av[4] = { av0[0], av0[1], av1[0], av1[1] };
        ull bd[4] = { dup2(bq.x), dup2(bq.y), dup2(bq.z), dup2(bq.w) };
        #pragma unroll
        for (int rp = 0; rp < 4; rp++)
            #pragma unroll
            for (int c = 0; c < 4; c++)
                acc2[rp][c] = fma2(av[rp], bd[c], acc2[rp][c]);
    }

    // Epilogue: unpack row pairs, add bias, store [b][h][i][d]
    float* outbase = ((ct < 4) ? g_fs : g_fd)
                   + (size_t)b * HH * FDIM * DOUT + (size_t)(ct & 3) * FDIM * DOUT;
    float bv[4];
    #pragma unroll
    for (int c = 0; c < 4; c++) bv[c] = bias[c0 + cx * 4 + c];

    #pragma unroll
    for (int rp = 0; rp < 4; rp++) {
        float2 p0 = u2f(acc2[rp][0]);
        float2 p1 = u2f(acc2[rp][1]);
        float2 p2 = u2f(acc2[rp][2]);
        float2 p3 = u2f(acc2[rp][3]);
        int r_lo = ry * 8 + 2 * rp;
        float* row0 = outbase + (size_t)r_lo * DOUT + cx * 4;
        float* row1 = row0 + DOUT;
        *(float4*)row0 = make_float4(p0.x + bv[0], p1.x + bv[1], p2.x + bv[2], p3.x + bv[3]);
        *(float4*)row1 = make_float4(p0.y + bv[0], p1.y + bv[1], p2.y + bv[2], p3.y + bv[3]);
    }
}

// ---------------------------------------------------------------------------
// Kernel 2: fused scores + softmax + aggregation, one CTA per (b,h).
//
// Exact rewrite: sum_d a_d * lrelu(fs_id + fd_jd, 0.2)
//              = 0.6*(As[i] + Ad[j]) + sum_d (0.4*a_d) * |fs_id + fd_jd|
// The |.| sum is computed with d packed into f32x2 pairs (lo = even d,
// hi = odd d; halves summed at the end): ADD2 + FFMA2 on the fma pipe,
// abs via 64-bit AND (2x LOP3) on the alu pipe.
//
// smem: fsN/fdN row-major [i][d] stride 130 (8B-aligned packed LDS.64).
// ---------------------------------------------------------------------------
#define NSTRIDE 130

__global__ __launch_bounds__(256, 2)
void attn_kernel(const float* __restrict__ attn)
{
    extern __shared__ float sm[];
    float* fsN   = sm;                     // [64 i][130]
    float* fdN   = fsN + FDIM * NSTRIDE;   // [64 j][130]
    float* attn4 = fdN + FDIM * NSTRIDE;   // 128  (0.4 * attn[h])
    float* attnv = attn4 + 128;            // 128
    float* As_s  = attnv + 128;            // 64
    float* Ad_s  = As_s + 64;              // 64
    float* prob  = Ad_s + 64;              // [64 j][64 i]

    const int bh   = blockIdx.x;           // b*4 + h
    const int h    = bh & 3;
    const int t    = threadIdx.x;
    const int lane = t & 31;
    const int w    = t >> 5;

    const float* fs = g_fs + (size_t)bh * FDIM * DOUT;
    const float* fd = g_fd + (size_t)bh * FDIM * DOUT;

    // Stage fs/fd (row-major, padded stride)
    for (int idx = t; idx < FDIM * DOUT; idx += 256) {
        int i = idx >> 7, d = idx & 127;
        fsN[i * NSTRIDE + d] = fs[idx];
        fdN[i * NSTRIDE + d] = fd[idx];
    }
    if (t < 128) {
        float a = attn[h * 128 + t];
        attnv[t] = a;
        attn4[t] = 0.4f * a;
    }
    __syncthreads();

    // As[i] = sum_d attn[d]*fs[i,d];  Ad[j] likewise
    if (t < 64) {
        float s = 0.f;
        #pragma unroll 4
        for (int d = 0; d < 128; d++) s = fmaf(attnv[d], fsN[t * NSTRIDE + d], s);
        As_s[t] = s;
    } else if (t < 128) {
        int j = t - 64;
        float s = 0.f;
        #pragma unroll 4
        for (int d = 0; d < 128; d++) s = fmaf(attnv[d], fdN[j * NSTRIDE + d], s);
        Ad_s[j] = s;
    }
    __syncthreads();

    // ---- Score phase: warp w owns j = w*8..w*8+7; lane owns i = lane, lane+32.
    // d packed in pairs: acc2 lo accumulates even d, hi odd d.
    const int jb = w * 8;
    const int i0 = lane, i1 = lane + 32;
    ull acc0[8], acc1[8];
    #pragma unroll
    for (int jj = 0; jj < 8; jj++) { acc0[jj] = 0ULL; acc1[jj] = 0ULL; }

    #pragma unroll 2
    for (int dp = 0; dp < 64; dp++) {
        ull a42 = *(const ull*)&attn4[2 * dp];               // broadcast
        ull f20 = *(const ull*)&fsN[i0 * NSTRIDE + 2 * dp];
        ull f21 = *(const ull*)&fsN[i1 * NSTRIDE + 2 * dp];
        #pragma unroll
        for (int jj = 0; jj < 8; jj++) {
            ull fd2 = *(const ull*)&fdN[(jb + jj) * NSTRIDE + 2 * dp];  // broadcast
            acc0[jj] = fma2(a42, abs2(add2(f20, fd2)), acc0[jj]);
            acc1[jj] = fma2(a42, abs2(add2(f21, fd2)), acc1[jj]);
        }
    }

    // ---- Softmax over i (64 sources) per j
    const float As0 = As_s[i0], As1 = As_s[i1];
    #pragma unroll
    for (int jj = 0; jj < 8; jj++) {
        float Adv = Ad_s[jb + jj];
        float2 h0 = u2f(acc0[jj]);
        float2 h1 = u2f(acc1[jj]);
        float s0 = 0.6f * (As0 + Adv) + (h0.x + h0.y);
        float s1 = 0.6f * (As1 + Adv) + (h1.x + h1.y);
        float m = fmaxf(s0, s1);
        #pragma unroll
        for (int o = 16; o; o >>= 1) m = fmaxf(m, __shfl_xor_sync(0xffffffffu, m, o));
        float e0 = __expf(s0 - m);
        float e1 = __expf(s1 - m);
        float ssum = e0 + e1;
        #pragma unroll
        for (int o = 16; o; o >>= 1) ssum += __shfl_xor_sync(0xffffffffu, ssum, o);
        float inv = __frcp_rn(ssum);
        prob[(jb + jj) * 64 + i0] = e0 * inv;
        prob[(jb + jj) * 64 + i1] = e1 * inv;
    }
    __syncwarp();

    // ---- Aggregation: lane owns d-pairs d' = lane + 32*dd (dd=0..1),
    // i.e. d = 2d', 2d'+1.  o2 += dup(p) * fs2, packed over d.
    ull o2[8][2];
    #pragma unroll
    for (int jj = 0; jj < 8; jj++) { o2[jj][0] = 0ULL; o2[jj][1] = 0ULL; }

    #pragma unroll 2
    for (int i = 0; i < 64; i++) {
        ull f20 = *(const ull*)&fsN[i * NSTRIDE + 2 * lane];
        ull f21 = *(const ull*)&fsN[i * NSTRIDE + 2 * (lane + 32)];
        #pragma unroll
        for (int jj = 0; jj < 8; jj++) {
            ull pd = dup2(prob[(jb + jj) * 64 + i]);   // broadcast + dup
            o2[jj][0] = fma2(pd, f20, o2[jj][0]);
            o2[jj][1] = fma2(pd, f21, o2[jj][1]);
        }
    }

    float* oh = g_oh + (size_t)bh * FDIM * DOUT;
    #pragma unroll
    for (int jj = 0; jj < 8; jj++) {
        *(float2*)&oh[(jb + jj) * DOUT + 2 * lane]        = u2f(o2[jj][0]);
        *(float2*)&oh[(jb + jj) * DOUT + 2 * (lane + 32)] = u2f(o2[jj][1]);
    }
}

// ---------------------------------------------------------------------------
// Kernel 3: mean over heads + transpose.  out[b, d, j] = 0.25 * sum_h oh[b,h,j,d]
// ---------------------------------------------------------------------------
__global__ __launch_bounds__(256)
void reduce_kernel(float* __restrict__ out)
{
    __shared__ float s[64 * 129];
    const int b = blockIdx.x;
    const int t = threadIdx.x;
    const float* oh = g_oh + (size_t)b * HH * FDIM * DOUT;

    for (int idx = t; idx < FDIM * DOUT; idx += 256) {
        int j = idx >> 7, d = idx & 127;
        float v = oh[idx] + oh[idx + 8192] + oh[idx + 16384] + oh[idx + 24576];
        s[j * 129 + d] = 0.25f * v;
    }
    __syncthreads();

    float* ob = out + (size_t)b * DOUT * FDIM;
    for (int idx = t; idx < DOUT * FDIM; idx += 256) {
        int j = idx & 63, d = idx >> 6;
        ob[idx] = s[j * 129 + d];
    }
}

// ---------------------------------------------------------------------------
extern "C" void kernel_launch(void* const* d_in, const int* in_sizes, int n_in,
                              void* d_out, int out_size)
{
    const float* x    = (const float*)d_in[0];
    const float* Wsrc = (const float*)d_in[1];
    const float* bsrc = (const float*)d_in[2];
    const float* Wdst = (const float*)d_in[3];
    const float* bdst = (const float*)d_in[4];
    const float* attn = (const float*)d_in[5];
    float* out = (float*)d_out;

    const int smem1 = (128 * 64 + 128 * 128) * 4;                               // 96 KB
    const int smem2 = (2 * FDIM * NSTRIDE + 128 + 128 + 64 + 64 + 4096) * 4;    // 84480 B

    cudaFuncSetAttribute(proj_kernel, cudaFuncAttributeMaxDynamicSharedMemorySize, smem1);
    cudaFuncSetAttribute(attn_kernel, cudaFuncAttributeMaxDynamicSharedMemorySize, smem2);

    proj_kernel<<<dim3(BB, 8), 256, smem1>>>(x, Wsrc, bsrc, Wdst, bdst);
    attn_kernel<<<BB * HH, 256, smem2>>>(attn);
    reduce_kernel<<<BB, 256>>>(out);
}